// round 1
// baseline (speedup 1.0000x reference)
#include <cuda_runtime.h>
#include <cuda_bf16.h>

// Problem constants (fixed by the reference)
#define Cc    8
#define Ll    4096
#define Ff    32
#define Kk    10
#define PROC  20
#define STEP  5
#define NW    815          // == CHAN_OUT, no pad region
#define WPB   256          // windows per block
#define NTILE 4            // ceil(815/256)

// Shared x tile: covers WPB windows -> WPB*STEP + (PROC-STEP) = 1295 floats
#define SXN (WPB * STEP + PROC - STEP)

__global__ __launch_bounds__(WPB, 2)
void dtw_kernel(const float* __restrict__ x,
                const float* __restrict__ kernels,
                float* __restrict__ out)
{
    const int tile = blockIdx.x;          // window tile [0, NTILE)
    const int f    = blockIdx.y;          // filter     [0, Ff)
    const int bc   = blockIdx.z;          // b*C + c    [0, 64)
    const int tid  = threadIdx.x;

    __shared__ float sx[SXN];

    // Cooperative, coalesced load of the x tile for this (b,c)
    const int    base = tile * WPB * STEP;
    const float* xc   = x + (size_t)bc * Ll;
    #pragma unroll
    for (int i = tid; i < SXN; i += WPB) {
        int g = base + i;
        sx[i] = (g < Ll) ? xc[g] : 0.0f;
    }
    __syncthreads();

    // Kernel taps: warp-uniform addresses -> broadcast loads, L1-resident
    float ker[Kk];
    #pragma unroll
    for (int i = 0; i < Kk; i++) ker[i] = __ldg(&kernels[f * Kk + i]);

    // Window: stride-5 shared reads, gcd(5,32)=1 -> conflict-free
    float w[PROC];
    #pragma unroll
    for (int j = 0; j < PROC; j++) w[j] = sx[tid * STEP + j];

    // DTW table, row-sweep with register-resident row of length PROC.
    float acc[PROC];

    // Row 0: cumulative sum of squared diffs
    float d = ker[0] - w[0];
    acc[0] = d * d;
    #pragma unroll
    for (int j = 1; j < PROC; j++) {
        d = ker[0] - w[j];
        acc[j] = fmaf(d, d, acc[j - 1]);
    }

    // Rows 1..K-1: acc[j] = d + min(left, up, diag); min(up,diag) is off the
    // left-dependency chain so the serial path is FMNMX+FFMA = 8 cyc/cell.
    #pragma unroll
    for (int i = 1; i < Kk; i++) {
        const float kv = ker[i];
        float diag = acc[0];              // old prev[0]
        d = kv - w[0];
        acc[0] = fmaf(d, d, acc[0]);      // new[0] = d + prev[0]
        #pragma unroll
        for (int j = 1; j < PROC; j++) {
            float up = acc[j];            // prev[j]
            float m  = fminf(fminf(acc[j - 1], up), diag);
            d = kv - w[j];
            acc[j] = fmaf(d, d, m);
            diag = up;                    // prev[j] becomes diag for j+1
        }
    }

    // Output layout: out[b, c*F + f, w] = ((bc)*F + f)*NW + w  (coalesced in w)
    const int wg = tile * WPB + tid;
    if (wg < NW) {
        out[((size_t)bc * Ff + f) * NW + wg] = acc[PROC - 1];
    }
}

extern "C" void kernel_launch(void* const* d_in, const int* in_sizes, int n_in,
                              void* d_out, int out_size)
{
    const float* x       = (const float*)d_in[0];   // (8, 8, 4096) f32
    const float* kernels = (const float*)d_in[1];   // (32, 10) f32
    float*       out     = (float*)d_out;           // (8, 256, 815) f32

    (void)in_sizes; (void)n_in; (void)out_size;

    dim3 grid(NTILE, Ff, 8 * Cc);   // (4, 32, 64)
    dtw_kernel<<<grid, WPB>>>(x, kernels, out);
}